// round 17
// baseline (speedup 1.0000x reference)
#include <cuda_runtime.h>
#include <cuda_fp16.h>
#include <math_constants.h>
#include <cstdint>

// Problem: z [32,256,32,32], embedding [1024,256]
constexpr int D    = 256;
constexpr int K    = 1024;
constexpr int HW   = 1024;
constexpr int NTOK = 32768;
constexpr int TM   = 128;        // tokens per CTA
constexpr int NB   = 32;         // codes per chunk
constexpr int NCHK = K / NB;     // 32
constexpr int CAP  = 6;          // candidate cap per half
#define MARGIN 1.25f

// ---- pass1 smem (u32 units) ----
constexpr int S1_AHI = 0;        // [128][128] u32 hi   64KB
constexpr int S1_B   = 16384;    // 2 x [32][128] u32   32KB
constexpr int S1_EH  = 24576;    // 1024 f32
constexpr int S1_DST = 25600;    // 32 x 132 f32
constexpr int S1_U32 = 29824;
constexpr int S1_BYTES = S1_U32 * 4;      // 119296

// ---- pass2 smem (u32 units) ----
constexpr int S2_Z   = 0;        // [256 d][128 tok] f32  128KB
constexpr int S2_C   = 32768;    // 2 x 4096 f32 (chunk pair)
constexpr int S2_RV  = 40960;    // 256
constexpr int S2_RI  = 41216;    // 256
constexpr int S2_LST = 41472;    // 2*128*CAP int
constexpr int S2_M   = 43008;    // 128
constexpr int S2_U32 = 43136;
constexpr int S2_BYTES = S2_U32 * 4;      // 172544

// ---- device scratch ----
__device__ __align__(16) uint32_t g_Ahi[NTOK * 128];   // half2 hi of z
__device__ __align__(16) uint32_t g_Bhi[K * 128];      // half2 hi of emb
__device__ __align__(16) float g_Dapp[(size_t)NTOK * K];  // approx dists, 134MB
__device__ __align__(16) float g_dw[K * D];
__device__ float g_counts[K];
__device__ float g_loss;
__device__ float g_eh[K];                // 0.5*||e_k||^2

// ---------------- helpers ----------------
__device__ __forceinline__ uint32_t smaddr(const void* p) {
    uint32_t a;
    asm("{ .reg .u64 t; cvta.to.shared.u64 t, %1; cvt.u32.u64 %0, t; }"
        : "=r"(a) : "l"(p));
    return a;
}
__device__ __forceinline__ void cp16(uint32_t s, const void* g) {
    asm volatile("cp.async.cg.shared.global [%0], [%1], 16;" :: "r"(s), "l"(g));
}
__device__ __forceinline__ void ldsm4(uint32_t* r, uint32_t addr) {
    asm volatile("ldmatrix.sync.aligned.m8n8.x4.shared.b16 {%0,%1,%2,%3}, [%4];"
        : "=r"(r[0]), "=r"(r[1]), "=r"(r[2]), "=r"(r[3]) : "r"(addr));
}
__device__ __forceinline__ void mma_f16(float* c, const uint32_t* a,
                                        const uint32_t* b) {
    asm volatile("mma.sync.aligned.m16n8k16.row.col.f32.f16.f16.f32 "
        "{%0,%1,%2,%3},{%4,%5,%6,%7},{%8,%9},{%0,%1,%2,%3};"
        : "+f"(c[0]), "+f"(c[1]), "+f"(c[2]), "+f"(c[3])
        : "r"(a[0]), "r"(a[1]), "r"(a[2]), "r"(a[3]), "r"(b[0]), "r"(b[1]));
}

// ---------------- split z -> fp16 hi, token-major (half grid per call) ----
__global__ void k_split_z(const float* __restrict__ z, int blk0) {
    const int tid  = threadIdx.x;
    const int blk  = blockIdx.x + blk0;
    const int b    = blk >> 2;
    const int toff = ((blk & 3) << 8) + tid;
    const int tok  = (b << 10) + toff;
    const float* zp = z + (size_t)b * D * HW + toff;
    uint4* Oh = reinterpret_cast<uint4*>(g_Ahi) + (size_t)tok * 32;
    for (int g = 0; g < 32; g++) {
        uint32_t hv[4];
        #pragma unroll
        for (int q = 0; q < 4; q++) {
            int d0 = (g * 4 + q) * 2;
            __half2 h = __floats2half2_rn(zp[(size_t)d0 * HW],
                                          zp[(size_t)(d0 + 1) * HW]);
            hv[q] = *reinterpret_cast<uint32_t*>(&h);
        }
        Oh[g] = make_uint4(hv[0], hv[1], hv[2], hv[3]);
    }
}

// ---------------- split emb -> fp16 hi + 0.5*||e||^2 ----------------
__global__ void k_split_emb(const float* __restrict__ emb) {
    const int wid  = threadIdx.x >> 5, lane = threadIdx.x & 31;
    const int code = blockIdx.x * 8 + wid;
    const float4* r = reinterpret_cast<const float4*>(emb + (size_t)code * D)
                    + lane * 2;
    float4 a = r[0], bq = r[1];
    float v[8] = {a.x, a.y, a.z, a.w, bq.x, bq.y, bq.z, bq.w};
    float s = 0.0f;
    uint32_t hv[4];
    #pragma unroll
    for (int q = 0; q < 4; q++) {
        s += v[2*q] * v[2*q] + v[2*q+1] * v[2*q+1];
        __half2 h = __floats2half2_rn(v[2*q], v[2*q+1]);
        hv[q] = *reinterpret_cast<uint32_t*>(&h);
    }
    reinterpret_cast<uint4*>(g_Bhi)[(size_t)code * 32 + lane] =
        make_uint4(hv[0], hv[1], hv[2], hv[3]);
    #pragma unroll
    for (int o = 16; o > 0; o >>= 1) s += __shfl_xor_sync(0xffffffffu, s, o);
    if (lane == 0) g_eh[code] = 0.5f * s;
}

// ---- pass1: hi-only HMMA GEMM, writes all approx distances ----
// 16 warps; warp = 16 tokens x 16 codes; A register-resident.
__global__ __launch_bounds__(512, 1)
void k_gemm() {
    extern __shared__ uint32_t sm[];
    const uint32_t sbase = smaddr(sm);
    float* Eh  = reinterpret_cast<float*>(sm + S1_EH);
    float* Dst = reinterpret_cast<float*>(sm + S1_DST);

    const int tid  = threadIdx.x;
    const int wid  = tid >> 5;
    const int lane = tid & 31;
    const int tok0 = blockIdx.x * TM;
    float* dapp = g_Dapp + (size_t)blockIdx.x * (K * TM);

    // ---- prologue: stage A hi (swizzled) + B chunk0 + Eh ----
    #pragma unroll
    for (int i = 0; i < 8; i++) {
        int grp = tid + 512 * i;                      // 4096 float4
        int row = grp >> 5, g4 = (grp & 31) << 2;
        const uint32_t* src = g_Ahi + (size_t)(tok0 + row) * 128 + g4;
        uint32_t dst = sbase
            + (S1_AHI + row * 128 + (g4 ^ ((row & 7) << 2))) * 4;
        cp16(dst, src);
    }
    #pragma unroll
    for (int i = 0; i < 2; i++) {                     // 1024 float4
        int grp = tid + 512 * i;
        int row = grp >> 5, g4 = (grp & 31) << 2;
        const uint32_t* src = g_Bhi + (size_t)row * 128 + g4;
        uint32_t dst = sbase
            + (S1_B + row * 128 + (g4 ^ ((row & 7) << 2))) * 4;
        cp16(dst, src);
    }
    asm volatile("cp.async.commit_group;" ::: "memory");
    for (int i = tid; i < K; i += 512) Eh[i] = g_eh[i];
    asm volatile("cp.async.wait_group 0;" ::: "memory");
    __syncthreads();

    // ldmatrix lane geometry
    const int j  = lane >> 3;
    const int r8 = lane & 7;
    const int tg = wid >> 1;        // token group 0..7
    const int ch = wid & 1;         // code half 0/1
    const uint32_t ax  = (uint32_t)(r8 << 2);
    const uint32_t jjA = (uint32_t)((j >> 1) << 2);
    const uint32_t jbB = (uint32_t)((j & 1) << 2);
    const uint32_t aRow = (uint32_t)((tg * 16 + (j & 1) * 8 + r8) * 128);
    const uint32_t bRow = (uint32_t)((ch * 16 + (j >> 1) * 8 + r8) * 128);

    // A fragments register-resident (64 regs)
    const uint32_t aH = sbase + (uint32_t)S1_AHI * 4;
    uint32_t ahAll[16][4];
    #pragma unroll
    for (int ks = 0; ks < 16; ks++) {
        const uint32_t tA = ((uint32_t)(ks * 8) + jjA) ^ ax;
        ldsm4(ahAll[ks], aH + (aRow + tA) * 4);
    }

    for (int c = 0; c < NCHK; c++) {
        if (c + 1 < NCHK) {
            const int code0 = (c + 1) * NB;
            const uint32_t bufo = (uint32_t)(S1_B + ((c + 1) & 1) * 4096);
            #pragma unroll
            for (int i = 0; i < 2; i++) {
                int grp = tid + 512 * i;
                int row = grp >> 5, g4 = (grp & 31) << 2;
                const uint32_t* src = g_Bhi + (size_t)(code0 + row) * 128 + g4;
                uint32_t dst = sbase
                    + (bufo + row * 128 + (g4 ^ ((row & 7) << 2))) * 4;
                cp16(dst, src);
            }
            asm volatile("cp.async.commit_group;" ::: "memory");
        }

        const uint32_t bB = sbase + (uint32_t)(S1_B + (c & 1) * 4096) * 4;
        float acc[2][4];
        #pragma unroll
        for (int nt = 0; nt < 2; nt++)
            #pragma unroll
            for (int e = 0; e < 4; e++) acc[nt][e] = 0.0f;

        #pragma unroll
        for (int ks = 0; ks < 16; ks++) {
            const uint32_t tB = ((uint32_t)(ks * 8) + jbB) ^ ax;
            uint32_t bh2[4];
            ldsm4(bh2, bB + (bRow + tB) * 4);
            mma_f16(acc[0], ahAll[ks], bh2);
            mma_f16(acc[1], ahAll[ks], bh2 + 2);
        }

        // fold: approx dist -> Dst[code_local*132 + row]
        const int cb = c * NB;
        #pragma unroll
        for (int nt = 0; nt < 2; nt++)
            #pragma unroll
            for (int e = 0; e < 4; e++) {
                int cl  = ch * 16 + nt * 8 + 2 * (lane & 3) + (e & 1);
                int row = tg * 16 + (e >> 1) * 8 + (lane >> 2);
                Dst[cl * 132 + row] = Eh[cb + cl] - acc[nt][e];
            }
        __syncthreads();
        // copy Dst -> gmem (coalesced 512B rows)
        #pragma unroll
        for (int i = 0; i < 8; i++) {
            int idx = tid + 512 * i;            // 4096
            int cl = idx >> 7, t = idx & 127;
            dapp[(size_t)(cb + cl) * TM + t] = Dst[cl * 132 + t];
        }
        if (c + 1 < NCHK)
            asm volatile("cp.async.wait_group 0;" ::: "memory");
        __syncthreads();
    }
}

// ---- pass2: min scan + candidate collect + exact recheck + scatter ----
__global__ __launch_bounds__(256, 1)
void k_refine(const float* __restrict__ z, const float* __restrict__ emb,
              float* __restrict__ out_idx, float* __restrict__ out_zq) {
    extern __shared__ uint32_t sm[];
    float* Zs  = reinterpret_cast<float*>(sm + S2_Z);    // [d][tok]
    float* Cs  = reinterpret_cast<float*>(sm + S2_C);    // 2 x 4096
    float* Rv  = reinterpret_cast<float*>(sm + S2_RV);
    int*   Ri  = reinterpret_cast<int*>(sm + S2_RI);
    int*   LST = reinterpret_cast<int*>(sm + S2_LST);
    float* ML  = reinterpret_cast<float*>(sm + S2_M);
    float* RED = reinterpret_cast<float*>(sm + S2_C);    // alias (after scans)

    const int tid  = threadIdx.x;
    const int tok0 = blockIdx.x * TM;
    const int b    = tok0 >> 10;
    const int toff = tok0 & 1023;
    const int t    = tid & 127;
    const int h    = tid >> 7;            // code half: 0 -> [0,512), 1 -> [512,1024)
    const float* dapp = g_Dapp + (size_t)blockIdx.x * (K * TM);

    // load z tile fp32, d-major
    {
        const float* zb = z + (size_t)b * D * HW + toff;
        int t4 = tid & 31, dr = tid >> 5;
        #pragma unroll 4
        for (int d = dr; d < D; d += 8) {
            float4 v = *reinterpret_cast<const float4*>(zb + (size_t)d * HW + (t4 << 2));
            *reinterpret_cast<float4*>(Zs + d * TM + (t4 << 2)) = v;
        }
    }
    __syncthreads();

    // ---- phase 1: min over approx distances ----
    float mymin = CUDART_INF_F;
    for (int cc = 0; cc < 16; cc++) {
        #pragma unroll
        for (int i = 0; i < 8; i++) {     // 2048 float4: chunks cc and cc+16
            int grp = tid + 256 * i;
            int c2 = grp >> 10, off = grp & 1023;
            float4 v = *reinterpret_cast<const float4*>(
                dapp + (size_t)(cc + c2 * 16) * NB * TM + off * 4);
            *reinterpret_cast<float4*>(Cs + c2 * 4096 + off * 4) = v;
        }
        __syncthreads();
        #pragma unroll
        for (int cl = 0; cl < 32; cl++) {
            float v = Cs[h * 4096 + cl * TM + t];
            if (v < mymin) mymin = v;
        }
        __syncthreads();
    }
    Rv[h * 128 + t] = mymin;
    __syncthreads();
    if (tid < TM) ML[tid] = fminf(Rv[tid], Rv[128 + tid]);
    __syncthreads();
    const float thresh = ML[t] + MARGIN;

    // ---- phase 2: collect candidates (ascending code order per half) ----
    int cnt = 0;
    for (int cc = 0; cc < 16; cc++) {
        #pragma unroll
        for (int i = 0; i < 8; i++) {
            int grp = tid + 256 * i;
            int c2 = grp >> 10, off = grp & 1023;
            float4 v = *reinterpret_cast<const float4*>(
                dapp + (size_t)(cc + c2 * 16) * NB * TM + off * 4);
            *reinterpret_cast<float4*>(Cs + c2 * 4096 + off * 4) = v;
        }
        __syncthreads();
        #pragma unroll
        for (int cl = 0; cl < 32; cl++) {
            if (Cs[h * 4096 + cl * TM + t] <= thresh) {
                if (cnt < CAP) LST[(h * 128 + t) * CAP + cnt] =
                    (h * 16 + cc) * NB + cl;
                cnt++;
            }
        }
        __syncthreads();
    }

    // ---- phase 3: exact fp32 recheck ----
    float bv = CUDART_INF_F; int bc = 0;
    auto exact = [&](int code) -> float {
        const float4* er = reinterpret_cast<const float4*>(emb + (size_t)code * D);
        float s = 0.0f;
        #pragma unroll 8
        for (int q = 0; q < 64; q++) {
            float4 e4 = __ldg(er + q);
            float d0 = Zs[(q * 4 + 0) * TM + t] - e4.x;
            float d1 = Zs[(q * 4 + 1) * TM + t] - e4.y;
            float d2 = Zs[(q * 4 + 2) * TM + t] - e4.z;
            float d3 = Zs[(q * 4 + 3) * TM + t] - e4.w;
            s += d0 * d0 + d1 * d1 + d2 * d2 + d3 * d3;
        }
        return s;
    };
    if (cnt <= CAP) {
        for (int i = 0; i < cnt; i++) {
            int code = LST[(h * 128 + t) * CAP + i];
            float dv = exact(code);
            if (dv < bv) { bv = dv; bc = code; }
        }
    } else {    // overflow fallback: exact-scan entire half (correct, ~never)
        for (int code = h * 512; code < h * 512 + 512; code++) {
            float dv = exact(code);
            if (dv < bv) { bv = dv; bc = code; }
        }
    }
    Rv[h * 128 + t] = bv;
    Ri[h * 128 + t] = bc;
    __syncthreads();
    if (tid < TM) {     // half0 codes < half1: ties keep half0 (lower index)
        float v0 = Rv[tid], v1 = Rv[128 + tid];
        int   bi = (v1 < v0) ? Ri[128 + tid] : Ri[tid];
        Ri[tid] = bi;
        out_idx[tok0 + tid] = (float)bi;
        atomicAdd(&g_counts[bi], 1.0f);
    }
    __syncthreads();

    // ---- phase 4: scatter z_q / loss / dw with exact fp32 z ----
    const int kk = Ri[t];
    const float* er  = emb + (size_t)kk * D;
    float*       dwr = g_dw + (size_t)kk * D;
    float*       qb  = out_zq + (size_t)b * D * HW + toff;
    float ls = 0.0f;
    for (int d0 = h * 128; d0 < h * 128 + 128; d0 += 2) {
        float zv0 = Zs[d0 * TM + t];
        float zv1 = Zs[(d0 + 1) * TM + t];
        float2 ev = *reinterpret_cast<const float2*>(er + d0);
        float df0 = ev.x - zv0, df1 = ev.y - zv1;
        qb[(size_t)d0 * HW + t]       = zv0 + df0;
        qb[(size_t)(d0 + 1) * HW + t] = zv1 + df1;
        ls += df0 * df0 + df1 * df1;
        atomicAdd(dwr + d0,     zv0);
        atomicAdd(dwr + d0 + 1, zv1);
    }
    RED[tid] = ls;
    __syncthreads();
    #pragma unroll
    for (int s = 128; s > 0; s >>= 1) {
        if (tid < s) RED[tid] += RED[tid + s];
        __syncthreads();
    }
    if (tid == 0) atomicAdd(&g_loss, RED[0]);
}

// ---------------- tail kernels (consume + re-zero scratch) ----------------
__global__ void k_cs(const float* __restrict__ ecs, float* __restrict__ out_cs) {
    __shared__ float part[32];
    int k = threadIdx.x, lane = k & 31, w = k >> 5;
    float cr = 0.99f * ecs[k] + 0.01f * g_counts[k];
    g_counts[k] = 0.0f;
    float s = cr;
    #pragma unroll
    for (int o = 16; o > 0; o >>= 1) s += __shfl_xor_sync(0xffffffffu, s, o);
    if (lane == 0) part[w] = s;
    __syncthreads();
    if (w == 0) {
        float tt = part[lane];
        #pragma unroll
        for (int o = 16; o > 0; o >>= 1) tt += __shfl_xor_sync(0xffffffffu, tt, o);
        if (lane == 0) part[0] = tt;
    }
    __syncthreads();
    float n = part[0];
    out_cs[k] = (cr + 1e-5f) / (n + (float)K * 1e-5f) * n;
}

// out_emaw/out_emb sit at odd float offsets in d_out -> scalar stores only.
__global__ void k_emb(const float* __restrict__ ema_w, const float* __restrict__ cs,
                      float* __restrict__ out_emaw, float* __restrict__ out_emb) {
    int i4 = (blockIdx.x * blockDim.x + threadIdx.x) * 4;
    if (i4 < K * D) {
        float4 w4 = *reinterpret_cast<const float4*>(ema_w + i4);
        float4 d4 = *reinterpret_cast<const float4*>(g_dw + i4);
        *reinterpret_cast<float4*>(g_dw + i4) = make_float4(0.f, 0.f, 0.f, 0.f);
        float inv = 1.0f / cs[i4 >> 8];
        float w0 = 0.99f * w4.x + 0.01f * d4.x;
        float w1 = 0.99f * w4.y + 0.01f * d4.y;
        float w2 = 0.99f * w4.z + 0.01f * d4.z;
        float w3 = 0.99f * w4.w + 0.01f * d4.w;
        out_emaw[i4 + 0] = w0;  out_emb[i4 + 0] = w0 * inv;
        out_emaw[i4 + 1] = w1;  out_emb[i4 + 1] = w1 * inv;
        out_emaw[i4 + 2] = w2;  out_emb[i4 + 2] = w2 * inv;
        out_emaw[i4 + 3] = w3;  out_emb[i4 + 3] = w3 * inv;
    }
}

__global__ void k_loss(float* __restrict__ out_loss) {
    if (threadIdx.x == 0) {
        out_loss[0] = 0.25f * g_loss / (float)((size_t)NTOK * D);
        g_loss = 0.0f;
    }
}

extern "C" void kernel_launch(void* const* d_in, const int* in_sizes, int n_in,
                              void* d_out, int out_size) {
    const float* z    = (const float*)d_in[0];
    const float* emb  = (const float*)d_in[1];
    const float* ecs  = (const float*)d_in[2];
    const float* emaw = (const float*)d_in[3];
    float* out = (float*)d_out;

    // output layout: z_q | idx | loss | new_embedding | cs | new_ema_w
    const size_t o_idx  = (size_t)NTOK * D;
    const size_t o_loss = o_idx + NTOK;
    const size_t o_emb  = o_loss + 1;
    const size_t o_cs   = o_emb + (size_t)K * D;
    const size_t o_emaw = o_cs + K;

    cudaFuncSetAttribute(k_gemm, cudaFuncAttributeMaxDynamicSharedMemorySize,
                         S1_BYTES);
    cudaFuncSetAttribute(k_refine, cudaFuncAttributeMaxDynamicSharedMemorySize,
                         S2_BYTES);

    // k_gemm is the 4th launch so ncu's bounded capture profiles it.
    k_split_emb <<<K / 8, 256>>>(emb);
    k_split_z   <<<64, 256>>>(z, 0);
    k_split_z   <<<64, 256>>>(z, 64);
    k_gemm      <<<NTOK / TM, 512, S1_BYTES>>>();
    k_refine    <<<NTOK / TM, 256, S2_BYTES>>>(z, emb, out + o_idx, out);
    k_cs        <<<1, K>>>(ecs, out + o_cs);
    k_emb       <<<K * D / 1024, 256>>>(emaw, out + o_cs,
                                        out + o_emaw, out + o_emb);
    k_loss      <<<1, 32>>>(out + o_loss);
}